// round 1
// baseline (speedup 1.0000x reference)
#include <cuda_runtime.h>
#include <math.h>

#define NB 8
#define CC 256
#define NPIX 1024
#define HEADS 8
#define HD 128
#define MQKV 3072
#define DIM 1024

// Hamilton tables
__constant__ int   c_IDX[16] = {0,1,2,3, 1,0,3,2, 2,3,0,1, 3,2,1,0};
__constant__ float c_SGN[16] = {1.f,-1.f,-1.f,-1.f, 1.f,1.f,1.f,-1.f,
                                1.f,-1.f,1.f,1.f, 1.f,1.f,-1.f,1.f};

// Scratch (device globals; no runtime allocation allowed)
__device__ float g_Weff[(size_t)MQKV*DIM];        // 12.6 MB
__device__ float g_Wproj[(size_t)DIM*DIM];        // 4.2 MB
__device__ float g_Q[(size_t)NB*HEADS*HD*NPIX];   // 33.5 MB  (B,H,d,N), pre-scaled
__device__ float g_K[(size_t)NB*HEADS*HD*NPIX];
__device__ float g_V[(size_t)NB*HEADS*HD*NPIX];
__device__ float g_O[(size_t)NB*DIM*NPIX];        // (B, ch=1024, N)

// ---------------------------------------------------------------------------
// Effective-weight prep (Hamilton sign/permutation folded into a dense matrix)
// ---------------------------------------------------------------------------
__global__ void prep_weff_kernel(const float* __restrict__ w_qkv){
  int idx = blockIdx.x*256 + threadIdx.x;        // MQKV*DIM total
  int g = idx >> 10, k = idx & 1023;
  int qc = g / 768, o = g - qc*768;
  int p = k >> 8, cch = k & 255;
  g_Weff[idx] = c_SGN[qc*4+p] * w_qkv[(c_IDX[qc*4+p]*768 + o)*256 + cch];
}

__global__ void prep_wproj_kernel(const float* __restrict__ w_proj){
  int idx = blockIdx.x*256 + threadIdx.x;        // DIM*DIM total
  int g = idx >> 10, k = idx & 1023;
  int qc = g >> 8, o = g & 255;
  int p = k >> 8, cch = k & 255;
  g_Wproj[idx] = c_SGN[qc*4+p] * w_proj[(c_IDX[qc*4+p]*256 + o)*256 + cch];
}

// ---------------------------------------------------------------------------
// Tiled SGEMM: C(M x 8192) = A(M x 1024) @ B(1024 x 8192)
// MODE 0: A=g_Weff (M=3072), B = gathered input x, epilogue scatters to Q/K/V
// MODE 1: A=g_Wproj (M=1024), B = g_O, epilogue writes final output (+bias)
// BM=BN=128, BK=16, 256 threads, 8x8 microtile.
// ---------------------------------------------------------------------------
template<int MODE>
__global__ __launch_bounds__(256) void sgemm_kernel(const float* __restrict__ Bsrc,
                                                    const float* __restrict__ bias,
                                                    float* __restrict__ outp){
  __shared__ float As[16][132];   // transposed A tile, padded
  __shared__ float Bs[16][128];

  const float* A = (MODE==0) ? g_Weff : g_Wproj;
  const float* Bp = (MODE==0) ? Bsrc : g_O;

  const int m0   = blockIdx.x * 128;
  const int col0 = blockIdx.y * 128;
  const int b    = col0 >> 10;        // batch (tiles never straddle: 1024 % 128 == 0)
  const int n0   = col0 & 1023;

  const int tid = threadIdx.x;
  const int ty = tid >> 4, tx = tid & 15;
  const int ar = tid >> 2;            // 0..63
  const int ac = (tid & 3) << 2;      // 0,4,8,12
  const int br = tid >> 5;            // 0..7
  const int bc = (tid & 31) << 2;     // 0..124

  float acc[8][8];
  #pragma unroll
  for (int i=0;i<8;i++)
    #pragma unroll
    for (int j=0;j<8;j++) acc[i][j] = 0.f;

  for (int kt=0; kt<64; kt++){
    const int k0 = kt << 4;
    // gmem loads to regs
    float4 a0 = *(const float4*)&A[(size_t)(m0+ar)*1024 + k0 + ac];
    float4 a1 = *(const float4*)&A[(size_t)(m0+ar+64)*1024 + k0 + ac];
    float4 b0, b1;
    if (MODE==0){
      int k = k0 + br; int p = k>>8; int cch = k & 255;
      b0 = *(const float4*)&Bp[((size_t)((b*CC+cch)*4 + p))*NPIX + n0 + bc];
      k = k0 + br + 8; p = k>>8; cch = k & 255;
      b1 = *(const float4*)&Bp[((size_t)((b*CC+cch)*4 + p))*NPIX + n0 + bc];
    } else {
      b0 = *(const float4*)&Bp[((size_t)b<<20) + (size_t)(k0+br)*1024 + n0 + bc];
      b1 = *(const float4*)&Bp[((size_t)b<<20) + (size_t)(k0+br+8)*1024 + n0 + bc];
    }
    __syncthreads();
    As[ac+0][ar] = a0.x; As[ac+1][ar] = a0.y; As[ac+2][ar] = a0.z; As[ac+3][ar] = a0.w;
    As[ac+0][ar+64] = a1.x; As[ac+1][ar+64] = a1.y; As[ac+2][ar+64] = a1.z; As[ac+3][ar+64] = a1.w;
    *(float4*)&Bs[br][bc]   = b0;
    *(float4*)&Bs[br+8][bc] = b1;
    __syncthreads();

    #pragma unroll
    for (int kk=0;kk<16;kk++){
      float a[8], bb[8];
      float4 t;
      t = *(const float4*)&As[kk][ty*8];   a[0]=t.x; a[1]=t.y; a[2]=t.z; a[3]=t.w;
      t = *(const float4*)&As[kk][ty*8+4]; a[4]=t.x; a[5]=t.y; a[6]=t.z; a[7]=t.w;
      t = *(const float4*)&Bs[kk][tx*8];   bb[0]=t.x; bb[1]=t.y; bb[2]=t.z; bb[3]=t.w;
      t = *(const float4*)&Bs[kk][tx*8+4]; bb[4]=t.x; bb[5]=t.y; bb[6]=t.z; bb[7]=t.w;
      #pragma unroll
      for (int i=0;i<8;i++)
        #pragma unroll
        for (int j=0;j<8;j++) acc[i][j] = fmaf(a[i], bb[j], acc[i][j]);
    }
  }

  // Epilogue
  if (MODE==0){
    const float qscale = 0.08838834764831845f;  // 1/sqrt(128)
    #pragma unroll
    for (int i=0;i<8;i++){
      int g = m0 + ty*8 + i;
      int qc = g / 768; int o = g - qc*768;
      int s = o >> 8; int cch = o & 255;
      int ch = (qc << 8) | cch;
      int h = ch >> 7, d = ch & 127;
      float bi = bias[g];
      float sc = (s==0) ? qscale : 1.f;
      float* dst = (s==0 ? g_Q : (s==1 ? g_K : g_V))
                 + ((size_t)((b*HEADS+h)*HD + d))*NPIX + n0 + tx*8;
      float4 o0 = make_float4((acc[i][0]+bi)*sc,(acc[i][1]+bi)*sc,(acc[i][2]+bi)*sc,(acc[i][3]+bi)*sc);
      float4 o1 = make_float4((acc[i][4]+bi)*sc,(acc[i][5]+bi)*sc,(acc[i][6]+bi)*sc,(acc[i][7]+bi)*sc);
      *(float4*)&dst[0] = o0;
      *(float4*)&dst[4] = o1;
    }
  } else {
    #pragma unroll
    for (int i=0;i<8;i++){
      int g = m0 + ty*8 + i;            // < 1024
      int qc = g >> 8; int cch = g & 255;
      float bi = bias[g];
      float* dst = outp + ((size_t)((b*CC+cch)*4 + qc))*NPIX + n0 + tx*8;
      float4 o0 = make_float4(acc[i][0]+bi,acc[i][1]+bi,acc[i][2]+bi,acc[i][3]+bi);
      float4 o1 = make_float4(acc[i][4]+bi,acc[i][5]+bi,acc[i][6]+bi,acc[i][7]+bi);
      *(float4*)&dst[0] = o0;
      *(float4*)&dst[4] = o1;
    }
  }
}

// ---------------------------------------------------------------------------
// Flash attention, fp32. One CTA = one (b,h) x 64-query block. 256 threads.
// Q,K,V in (B,H,d=128,N=1024); Q pre-scaled by 1/sqrt(d).
// ---------------------------------------------------------------------------
#define ATT_SMEM_FLOATS (8192 + 8192 + 64*133 + 64*68 + 64*3 + 256)

__global__ __launch_bounds__(256) void attn_kernel(){
  extern __shared__ float sm[];
  float* Qs  = sm;                 // [128][64]  Qs[d][n]
  float* Ks  = Qs  + 8192;         // [128][64]  Ks[d][m]
  float* Vts = Ks  + 8192;         // [64][133]  Vts[m][d]
  float* Ps  = Vts + 64*133;       // [64][68]
  float* s_m = Ps  + 64*68;        // [64]
  float* s_l = s_m + 64;           // [64]
  float* s_al= s_l + 64;           // [64]
  float* red = s_al+ 64;           // [256]

  const int tid = threadIdx.x;
  const int bh  = blockIdx.y;              // b*8+h
  const int n0  = blockIdx.x * 64;
  const float* qbase = g_Q + (size_t)bh * HD * NPIX;
  const float* kbase = g_K + (size_t)bh * HD * NPIX;
  const float* vbase = g_V + (size_t)bh * HD * NPIX;

  const int lr = tid >> 4;   // 0..15
  const int lc = tid & 15;   // 0..15

  // Load Q tile (coalesced)
  #pragma unroll
  for (int rep=0; rep<8; rep++){
    int d = rep*16 + lr;
    float4 v = *(const float4*)&qbase[(size_t)d*NPIX + n0 + lc*4];
    *(float4*)&Qs[d*64 + lc*4] = v;
  }
  if (tid < 64){ s_m[tid] = -1e30f; s_l[tid] = 0.f; }

  float accO[4][8];
  #pragma unroll
  for (int i=0;i<4;i++)
    #pragma unroll
    for (int j=0;j<8;j++) accO[i][j] = 0.f;

  const int row  = tid >> 2;    // softmax row ownership
  const int part = tid & 3;

  for (int mt=0; mt<16; mt++){
    const int m0 = mt*64;
    __syncthreads();   // protect Ks/Vts/Ps (and Qs on first iter)
    #pragma unroll
    for (int rep=0; rep<8; rep++){
      int d = rep*16 + lr;
      float4 kv = *(const float4*)&kbase[(size_t)d*NPIX + m0 + lc*4];
      *(float4*)&Ks[d*64 + lc*4] = kv;
      float4 vv = *(const float4*)&vbase[(size_t)d*NPIX + m0 + lc*4];
      Vts[(lc*4+0)*133 + d] = vv.x;
      Vts[(lc*4+1)*133 + d] = vv.y;
      Vts[(lc*4+2)*133 + d] = vv.z;
      Vts[(lc*4+3)*133 + d] = vv.w;
    }
    __syncthreads();

    // S = Q^T K  (64x64), 4x4 microtile
    float accS[4][4];
    #pragma unroll
    for (int i=0;i<4;i++)
      #pragma unroll
      for (int j=0;j<4;j++) accS[i][j] = 0.f;
    #pragma unroll 4
    for (int d=0; d<128; d++){
      float4 qv = *(const float4*)&Qs[d*64 + lr*4];
      float4 kv = *(const float4*)&Ks[d*64 + lc*4];
      float qa[4] = {qv.x,qv.y,qv.z,qv.w};
      float ka[4] = {kv.x,kv.y,kv.z,kv.w};
      #pragma unroll
      for (int i=0;i<4;i++)
        #pragma unroll
        for (int j=0;j<4;j++) accS[i][j] = fmaf(qa[i], ka[j], accS[i][j]);
    }
    #pragma unroll
    for (int i=0;i<4;i++)
      *(float4*)&Ps[(lr*4+i)*68 + lc*4] =
        make_float4(accS[i][0],accS[i][1],accS[i][2],accS[i][3]);
    __syncthreads();

    // online softmax
    float mx = -1e30f;
    #pragma unroll
    for (int m=0;m<16;m++) mx = fmaxf(mx, Ps[row*68 + part*16 + m]);
    red[tid] = mx;
    __syncthreads();
    if (tid < 64){
      float mnew = fmaxf(fmaxf(red[tid*4],red[tid*4+1]), fmaxf(red[tid*4+2],red[tid*4+3]));
      mnew = fmaxf(mnew, s_m[tid]);
      s_al[tid] = __expf(s_m[tid] - mnew);
      s_m[tid] = mnew;
    }
    __syncthreads();
    float mnew = s_m[row];
    float lsum = 0.f;
    #pragma unroll
    for (int m=0;m<16;m++){
      float e = __expf(Ps[row*68 + part*16 + m] - mnew);
      Ps[row*68 + part*16 + m] = e;
      lsum += e;
    }
    red[tid] = lsum;
    __syncthreads();
    if (tid < 64)
      s_l[tid] = s_l[tid]*s_al[tid] + (red[tid*4]+red[tid*4+1]+red[tid*4+2]+red[tid*4+3]);

    // O = alpha*O + P @ V^T
    #pragma unroll
    for (int i=0;i<4;i++){
      float a = s_al[lr*4+i];
      #pragma unroll
      for (int j=0;j<8;j++) accO[i][j] *= a;
    }
    for (int m4=0; m4<64; m4+=4){
      float pv[4][4];
      #pragma unroll
      for (int i=0;i<4;i++){
        float4 t = *(const float4*)&Ps[(lr*4+i)*68 + m4];
        pv[i][0]=t.x; pv[i][1]=t.y; pv[i][2]=t.z; pv[i][3]=t.w;
      }
      #pragma unroll
      for (int mi=0; mi<4; mi++){
        float vv[8];
        #pragma unroll
        for (int j=0;j<8;j++) vv[j] = Vts[(m4+mi)*133 + lc + 16*j];
        #pragma unroll
        for (int i=0;i<4;i++)
          #pragma unroll
          for (int j=0;j<8;j++) accO[i][j] = fmaf(pv[i][mi], vv[j], accO[i][j]);
      }
    }
  }
  __syncthreads();

  // Write O channel-major: g_O[b][h*128+d][n]
  const int h = bh & 7, b = bh >> 3;
  #pragma unroll
  for (int i=0;i<4;i++){
    int n = n0 + lr*4 + i;
    float inv = 1.f / s_l[lr*4+i];
    #pragma unroll
    for (int j=0;j<8;j++){
      int d = lc + 16*j;
      g_O[((size_t)b*DIM + h*HD + d)*NPIX + n] = accO[i][j]*inv;
    }
  }
}

// ---------------------------------------------------------------------------
// Quaternion depthwise 3x3, accumulates into final output.
// One CTA per (b,c): 256 threads, 4 pixels each, all 4 output components.
// ---------------------------------------------------------------------------
__global__ __launch_bounds__(256) void qdwconv_kernel(const float* __restrict__ x,
                                                      const float* __restrict__ w_pe,
                                                      const float* __restrict__ b_pe,
                                                      float* __restrict__ outp){
  __shared__ float xs[4][1024];
  __shared__ float wt[4][4][9];   // [qc][p][tap], sign folded
  const int bid = blockIdx.x;     // b*256 + c
  const int c = bid & 255, b = bid >> 8;
  const int tid = threadIdx.x;

  #pragma unroll
  for (int p=0;p<4;p++){
    const float* xp = x + ((size_t)((b*CC + c)*4 + p))*NPIX;
    for (int k=tid; k<1024; k+=256) xs[p][k] = xp[k];
  }
  if (tid < 144){
    int qc = tid/36, p = (tid/9)&3, t = tid%9;
    wt[qc][p][t] = c_SGN[qc*4+p] * w_pe[(c_IDX[qc*4+p]*CC + c)*9 + t];
  }
  __syncthreads();

  float bia[4];
  #pragma unroll
  for (int qc=0;qc<4;qc++) bia[qc] = b_pe[qc*CC + c];

  for (int k=tid; k<1024; k+=256){
    int hh = k >> 5, ww = k & 31;
    float acc[4] = {bia[0],bia[1],bia[2],bia[3]};
    #pragma unroll
    for (int p=0;p<4;p++){
      #pragma unroll
      for (int kh=0;kh<3;kh++){
        int h2 = hh + kh - 1;
        if (h2 < 0 || h2 > 31) continue;
        #pragma unroll
        for (int kw=0;kw<3;kw++){
          int w2 = ww + kw - 1;
          if (w2 < 0 || w2 > 31) continue;
          float xv = xs[p][h2*32 + w2];
          #pragma unroll
          for (int qc=0;qc<4;qc++) acc[qc] = fmaf(wt[qc][p][kh*3+kw], xv, acc[qc]);
        }
      }
    }
    #pragma unroll
    for (int qc=0;qc<4;qc++)
      outp[((size_t)((b*CC + c)*4 + qc))*NPIX + k] += acc[qc];
  }
}

// ---------------------------------------------------------------------------
extern "C" void kernel_launch(void* const* d_in, const int* in_sizes, int n_in,
                              void* d_out, int out_size){
  const float* x      = (const float*)d_in[0];
  const float* w_qkv  = (const float*)d_in[1];
  const float* b_qkv  = (const float*)d_in[2];
  const float* w_proj = (const float*)d_in[3];
  const float* b_proj = (const float*)d_in[4];
  const float* w_pe   = (const float*)d_in[5];
  const float* b_pe   = (const float*)d_in[6];
  float* outp = (float*)d_out;

  (void)in_sizes; (void)n_in; (void)out_size;

  const size_t att_smem = (size_t)ATT_SMEM_FLOATS * sizeof(float);
  cudaFuncSetAttribute(attn_kernel, cudaFuncAttributeMaxDynamicSharedMemorySize,
                       (int)att_smem);

  prep_weff_kernel <<< (MQKV*DIM)/256, 256 >>> (w_qkv);
  prep_wproj_kernel<<< (DIM*DIM)/256, 256 >>> (w_proj);

  // QKV: C(3072 x 8192)
  sgemm_kernel<0><<< dim3(24,64), 256 >>>(x, b_qkv, nullptr);

  // Attention: 16 query-blocks x 64 (b,h)
  attn_kernel<<< dim3(16,64), 256, att_smem >>>();

  // Proj: C(1024 x 8192) -> final output (+bias)
  sgemm_kernel<1><<< dim3(8,64), 256 >>>(nullptr, b_proj, outp);

  // Positional depthwise conv, accumulate
  qdwconv_kernel<<< NB*CC, 256 >>>(x, w_pe, b_pe, outp);
}